// round 6
// baseline (speedup 1.0000x reference)
#include <cuda_runtime.h>
#include <math.h>
#include <cstdint>

#define BB 8
#define CC 256
#define CIc 128
#define NN4 4096
#define MM 1024
#define EPSF 1e-5f
#define SCALE 0.08838834764831845f  // 1/sqrt(128)

// -------- scratch (static device globals; no allocation) --------
__device__ float d_xT[(size_t)BB*NN4*CC];    // x^T   (b, n, c)  merged rows
__device__ float d_xpT[(size_t)BB*MM*CC];    // pooled^T (b, m, c)
__device__ float d_thT[(size_t)BB*NN4*CIc];  // theta^T (b, n, ci)
__device__ float d_phT[(size_t)BB*MM*CIc];   // phi^T (b, m, ci)
__device__ float d_gT [(size_t)BB*MM*CIc];   // g^T (b, m, ci)
__device__ float d_s  [(size_t)BB*NN4*MM];   // scores/probs (b, q, m)
__device__ float d_tT [(size_t)BB*NN4*CIc];  // t^T (b, q, ci)
__device__ float d_zP [(size_t)CC*BB*NN4];   // z' (c, b, n)
__device__ float d_stats[2*CC];

// -------- helpers --------
__device__ __forceinline__ unsigned f2tf(float f){
    unsigned r; asm("cvt.rna.tf32.f32 %0, %1;" : "=r"(r) : "f"(f)); return r;
}
__device__ __forceinline__ void tfsplit(float v, unsigned &hi, unsigned &lo){
    hi = f2tf(v);
    lo = f2tf(v - __uint_as_float(hi));
}
__device__ __forceinline__ void mmaq(float c[4], const uint4& a, const uint2& b){
    asm("mma.sync.aligned.m16n8k8.row.col.f32.tf32.tf32.f32 "
        "{%0,%1,%2,%3},{%4,%5,%6,%7},{%8,%9},{%0,%1,%2,%3};"
        : "+f"(c[0]), "+f"(c[1]), "+f"(c[2]), "+f"(c[3])
        : "r"(a.x), "r"(a.y), "r"(a.z), "r"(a.w), "r"(b.x), "r"(b.y));
}

// -------- x transpose: (b,c,4096) -> (b,n,256) --------
__global__ void transpose_x(const float* __restrict__ x, float* __restrict__ xT){
    __shared__ float tile[32][33];
    int b = blockIdx.z;
    int n0 = blockIdx.x*32, c0 = blockIdx.y*32;
    int tx = threadIdx.x, ty = threadIdx.y;
    const float* xb = x + (size_t)b*CC*NN4;
    #pragma unroll
    for (int i = ty; i < 32; i += 8) tile[i][tx] = xb[(size_t)(c0+i)*NN4 + n0 + tx];
    __syncthreads();
    float* xtb = xT + (size_t)b*NN4*CC;
    #pragma unroll
    for (int i = ty; i < 32; i += 8) xtb[(size_t)(n0+i)*CC + c0 + tx] = tile[tx][i];
}

// -------- 2x2 maxpool on transposed layout --------
__global__ void poolT_kernel(const float* __restrict__ xT, float* __restrict__ xpT){
    int e = blockIdx.x*256 + threadIdx.x;    // < BB*MM*CC
    int c = e & 255; int bm = e >> 8;
    int m = bm & 1023; int b = bm >> 10;
    int i = m >> 5, j = m & 31;
    const float* base = xT + ((size_t)b*NN4 + (2*i)*64 + 2*j)*CC + c;
    xpT[e] = fmaxf(fmaxf(base[0], base[256]), fmaxf(base[64*256], base[65*256]));
}

// -------- unified mma.sync tf32 GEMM: D(128x128/CTA) = A(M,K) @ B(N,K)^T --------
// SMEM holds tiles in *fragment layout*: inner loop = wide LDS + MMA only.
// SPLIT3: 3xTF32 (hi/lo planes, 3 passes). BTRANS: B global is (K,N) row-major.
// BMODE: 0 none, 1 bias along M, 2 bias along N.  SCA: scale A by 1/sqrt(128).
template<int KFULL, int BMODE, bool SPLIT3, bool SCA, bool BTRANS>
__global__ __launch_bounds__(256, 2) void gemm_mma(
        const float* __restrict__ A, const float* __restrict__ B,
        const float* __restrict__ bias, float* __restrict__ Out,
        int ldA, int ldB, int ldOut, size_t sA, size_t sB, size_t sOut){
    extern __shared__ float sf[];
    float* Ah = sf;                                  // [8 mt][4 k8][32 ln][4]
    float* Bh = sf + 4096;                           // [16 nt][4 k8][32 ln][2]
    float* Al = SPLIT3 ? (sf + 8192)  : sf;
    float* Bl = SPLIT3 ? (sf + 12288) : sf;
    int b = blockIdx.z;
    int m0 = blockIdx.y*128, n0 = blockIdx.x*128;
    const float* Ab = A + (size_t)b*sA;
    const float* Bb = B + (size_t)b*sB;
    float* Ob = Out + (size_t)b*sOut;
    int tid = threadIdx.x, w = tid >> 5, lane = tid & 31;
    int gg = lane >> 2, t4 = lane & 3;
    float acc[2][8][4] = {};
    int wmt = (w >> 1)*2;      // A m-tile base (of 8)
    int wnt = (w & 1)*8;       // B n-tile base (of 16)

    #pragma unroll 1
    for (int ch = 0; ch < KFULL/32; ch++){
        int k0 = ch*32;
        __syncthreads();
        // ---- stage A: 4 fragment-quads per thread ----
        #pragma unroll
        for (int qq = 0; qq < 4; qq++){
            int Q = tid + 256*qq;
            int ln = Q & 31, k8 = (Q >> 5) & 3, mt = Q >> 7;
            int r = m0 + mt*16 + (ln >> 2);
            int kk = k0 + k8*8 + (ln & 3);
            float v0 = Ab[(size_t)r*ldA + kk];
            float v1 = Ab[(size_t)(r+8)*ldA + kk];
            float v2 = Ab[(size_t)r*ldA + kk + 4];
            float v3 = Ab[(size_t)(r+8)*ldA + kk + 4];
            if (SCA){ v0*=SCALE; v1*=SCALE; v2*=SCALE; v3*=SCALE; }
            if (SPLIT3){
                uint4 h, l;
                tfsplit(v0,h.x,l.x); tfsplit(v1,h.y,l.y);
                tfsplit(v2,h.z,l.z); tfsplit(v3,h.w,l.w);
                *(uint4*)(Ah + Q*4) = h;
                *(uint4*)(Al + Q*4) = l;
            } else {
                uint4 h = make_uint4(f2tf(v0), f2tf(v1), f2tf(v2), f2tf(v3));
                *(uint4*)(Ah + Q*4) = h;
            }
        }
        // ---- stage B: 8 fragment-pairs per thread ----
        #pragma unroll
        for (int pp = 0; pp < 8; pp++){
            int P = tid + 256*pp;
            int ln = P & 31, k8 = (P >> 5) & 3, nt = P >> 7;
            int n = n0 + nt*8 + (ln >> 2);
            int kk = k0 + k8*8 + (ln & 3);
            float v0, v1;
            if (!BTRANS){
                v0 = Bb[(size_t)n*ldB + kk];
                v1 = Bb[(size_t)n*ldB + kk + 4];
            } else {
                v0 = Bb[(size_t)kk*ldB + n];
                v1 = Bb[(size_t)(kk+4)*ldB + n];
            }
            if (SPLIT3){
                uint2 h, l;
                tfsplit(v0,h.x,l.x); tfsplit(v1,h.y,l.y);
                *(uint2*)(Bh + P*2) = h;
                *(uint2*)(Bl + P*2) = l;
            } else {
                uint2 h = make_uint2(f2tf(v0), f2tf(v1));
                *(uint2*)(Bh + P*2) = h;
            }
        }
        __syncthreads();
        // ---- compute: wide LDS + 3 independent MMA passes ----
        #pragma unroll
        for (int kc = 0; kc < 4; kc++){
            uint4 ah[2]; uint2 bh[8];
            #pragma unroll
            for (int mt = 0; mt < 2; mt++)
                ah[mt] = *(const uint4*)(Ah + (((wmt+mt)*4 + kc)*32 + lane)*4);
            #pragma unroll
            for (int nt = 0; nt < 8; nt++)
                bh[nt] = *(const uint2*)(Bh + (((wnt+nt)*4 + kc)*32 + lane)*2);
            #pragma unroll
            for (int mt = 0; mt < 2; mt++)
                #pragma unroll
                for (int nt = 0; nt < 8; nt++)
                    mmaq(acc[mt][nt], ah[mt], bh[nt]);
            if (SPLIT3){
                uint4 al[2];
                #pragma unroll
                for (int mt = 0; mt < 2; mt++)
                    al[mt] = *(const uint4*)(Al + (((wmt+mt)*4 + kc)*32 + lane)*4);
                #pragma unroll
                for (int mt = 0; mt < 2; mt++)
                    #pragma unroll
                    for (int nt = 0; nt < 8; nt++)
                        mmaq(acc[mt][nt], al[mt], bh[nt]);
                uint2 bl[8];
                #pragma unroll
                for (int nt = 0; nt < 8; nt++)
                    bl[nt] = *(const uint2*)(Bl + (((wnt+nt)*4 + kc)*32 + lane)*2);
                #pragma unroll
                for (int mt = 0; mt < 2; mt++)
                    #pragma unroll
                    for (int nt = 0; nt < 8; nt++)
                        mmaq(acc[mt][nt], ah[mt], bl[nt]);
            }
        }
    }
    // ---- epilogue ----
    #pragma unroll
    for (int mt = 0; mt < 2; mt++){
        int row0 = m0 + (wmt+mt)*16 + gg;
        float bm0 = (BMODE == 1) ? bias[row0]   : 0.f;
        float bm1 = (BMODE == 1) ? bias[row0+8] : 0.f;
        #pragma unroll
        for (int nt = 0; nt < 8; nt++){
            int col = (wnt+nt)*8 + 2*t4;         // local col within 128
            int gcol = n0 + col;
            float bn0 = (BMODE == 2) ? bias[gcol]   : 0.f;
            float bn1 = (BMODE == 2) ? bias[gcol+1] : 0.f;
            *(float2*)&Ob[(size_t)row0*ldOut + gcol] =
                make_float2(acc[mt][nt][0]+bm0+bn0, acc[mt][nt][1]+bm0+bn1);
            *(float2*)&Ob[(size_t)(row0+8)*ldOut + gcol] =
                make_float2(acc[mt][nt][2]+bm1+bn0, acc[mt][nt][3]+bm1+bn1);
        }
    }
}

// -------- softmax rows in place --------
__global__ void softmax_kernel(float* __restrict__ S){
    int row = blockIdx.x*8 + (threadIdx.x >> 5);
    int lane = threadIdx.x & 31;
    float4* rp = (float4*)(S + (size_t)row*MM);
    float4 v[8];
    float mx = -1e30f;
    #pragma unroll
    for (int j = 0; j < 8; j++){
        v[j] = rp[lane + 32*j];
        mx = fmaxf(mx, fmaxf(fmaxf(v[j].x, v[j].y), fmaxf(v[j].z, v[j].w)));
    }
    #pragma unroll
    for (int o = 16; o; o >>= 1) mx = fmaxf(mx, __shfl_xor_sync(0xffffffffu, mx, o));
    float sum = 0.f;
    #pragma unroll
    for (int j = 0; j < 8; j++){
        v[j].x = __expf(v[j].x - mx); v[j].y = __expf(v[j].y - mx);
        v[j].z = __expf(v[j].z - mx); v[j].w = __expf(v[j].w - mx);
        sum += v[j].x + v[j].y + v[j].z + v[j].w;
    }
    #pragma unroll
    for (int o = 16; o; o >>= 1) sum += __shfl_xor_sync(0xffffffffu, sum, o);
    float inv = 1.f/sum;
    #pragma unroll
    for (int j = 0; j < 8; j++){
        v[j].x *= inv; v[j].y *= inv; v[j].z *= inv; v[j].w *= inv;
        rp[lane + 32*j] = v[j];
    }
}

// -------- per-channel stats over z'(c, b*n): one block per channel --------
__global__ void stats_kernel(const float* __restrict__ zP, float* __restrict__ stats){
    __shared__ double sd[256], sd2[256];
    int c = blockIdx.x, tid = threadIdx.x;
    const float4* row = (const float4*)(zP + (size_t)c*BB*NN4);
    double s = 0.0, s2 = 0.0;
    for (int i = tid; i < BB*NN4/4; i += 256){
        float4 v = row[i];
        s  += (double)v.x + v.y + v.z + v.w;
        s2 += (double)v.x*v.x + (double)v.y*v.y + (double)v.z*v.z + (double)v.w*v.w;
    }
    sd[tid] = s; sd2[tid] = s2;
    __syncthreads();
    for (int o = 128; o; o >>= 1){
        if (tid < o){ sd[tid] += sd[tid+o]; sd2[tid] += sd2[tid+o]; }
        __syncthreads();
    }
    if (tid == 0){
        double cnt = (double)(BB*NN4);
        double mean = sd[0]/cnt;
        double var  = sd2[0]/cnt - mean*mean;
        stats[c]      = (float)mean;
        stats[CC + c] = rsqrtf((float)var + EPSF);
    }
}

// -------- normalize + affine + residual: out(b,c,n) from x(b,c,n), z'(c,b,n) --------
__global__ void finalize_kernel(const float* __restrict__ x, const float* __restrict__ zP,
                                const float* __restrict__ stats,
                                const float* __restrict__ gamma, const float* __restrict__ beta,
                                float* __restrict__ out){
    int i4 = blockIdx.x*256 + threadIdx.x;     // < BB*CC*NN4/4
    int n4 = i4 & 1023;
    int c  = (i4 >> 10) & 255;
    int b  = i4 >> 18;
    float a  = stats[CC + c] * gamma[c];
    float bc = beta[c] - stats[c]*a;
    float4 xv = ((const float4*)x)[i4];
    float4 zv = ((const float4*)zP)[((size_t)c*BB + b)*1024 + n4];
    float4 o;
    o.x = xv.x + zv.x*a + bc;
    o.y = xv.y + zv.y*a + bc;
    o.z = xv.z + zv.z*a + bc;
    o.w = xv.w + zv.w*a + bc;
    ((float4*)out)[i4] = o;
}

extern "C" void kernel_launch(void* const* d_in, const int* in_sizes, int n_in,
                              void* d_out, int out_size){
    const float* x       = (const float*)d_in[0];
    const float* theta_w = (const float*)d_in[1];
    const float* theta_b = (const float*)d_in[2];
    const float* phi_w   = (const float*)d_in[3];
    const float* phi_b   = (const float*)d_in[4];
    const float* g_w     = (const float*)d_in[5];
    const float* g_b     = (const float*)d_in[6];
    const float* wz_w    = (const float*)d_in[7];
    const float* wz_b    = (const float*)d_in[8];
    const float* gamma   = (const float*)d_in[9];
    const float* beta    = (const float*)d_in[10];
    float* out = (float*)d_out;

    float *xT, *xpT, *thT, *phT, *gT, *s, *tT, *zP, *stats;
    cudaGetSymbolAddress((void**)&xT,    d_xT);
    cudaGetSymbolAddress((void**)&xpT,   d_xpT);
    cudaGetSymbolAddress((void**)&thT,   d_thT);
    cudaGetSymbolAddress((void**)&phT,   d_phT);
    cudaGetSymbolAddress((void**)&gT,    d_gT);
    cudaGetSymbolAddress((void**)&s,     d_s);
    cudaGetSymbolAddress((void**)&tT,    d_tT);
    cudaGetSymbolAddress((void**)&zP,    d_zP);
    cudaGetSymbolAddress((void**)&stats, d_stats);

    const int SM1 = 32768, SM3 = 65536;
    cudaFuncSetAttribute(gemm_mma<256,2,false,false,false>,
        cudaFuncAttributeMaxDynamicSharedMemorySize, SM1);
    cudaFuncSetAttribute(gemm_mma<256,2,true,false,false>,
        cudaFuncAttributeMaxDynamicSharedMemorySize, SM3);
    cudaFuncSetAttribute(gemm_mma<128,0,false,true,false>,
        cudaFuncAttributeMaxDynamicSharedMemorySize, SM1);
    cudaFuncSetAttribute(gemm_mma<1024,0,true,false,true>,
        cudaFuncAttributeMaxDynamicSharedMemorySize, SM3);
    cudaFuncSetAttribute(gemm_mma<128,1,true,false,false>,
        cudaFuncAttributeMaxDynamicSharedMemorySize, SM3);

    transpose_x<<<dim3(NN4/32, CC/32, BB), dim3(32,8)>>>(x, xT);
    poolT_kernel<<<(BB*MM*CC)/256, 256>>>(xT, xpT);

    // theta^T (merged 32768 x 128) = xT @ theta_w^T  [1x tf32]
    gemm_mma<256,2,false,false,false><<<dim3(1, (BB*NN4)/128, 1), 256, SM1>>>(
        xT, theta_w, theta_b, thT, CC, CC, CIc, 0, 0, 0);
    // phi^T (merged 8192 x 128) [1x tf32]
    gemm_mma<256,2,false,false,false><<<dim3(1, (BB*MM)/128, 1), 256, SM1>>>(
        xpT, phi_w, phi_b, phT, CC, CC, CIc, 0, 0, 0);
    // g^T (merged 8192 x 128) [3x tf32 — feeds output linearly]
    gemm_mma<256,2,true,false,false><<<dim3(1, (BB*MM)/128, 1), 256, SM3>>>(
        xpT, g_w, g_b, gT, CC, CC, CIc, 0, 0, 0);
    // S (q,m) per batch = (thT*SCALE) @ phT^T  [1x tf32 — softmax damps]
    gemm_mma<128,0,false,true,false><<<dim3(MM/128, NN4/128, BB), 256, SM1>>>(
        thT, phT, theta_b, s, CIc, CIc, MM,
        (size_t)NN4*CIc, (size_t)MM*CIc, (size_t)NN4*MM);
    softmax_kernel<<<(BB*NN4)/8, 256>>>(s);
    // t^T (q,ci) per batch = P @ g  [3x tf32; B from gT via BTRANS]
    gemm_mma<1024,0,true,false,true><<<dim3(1, NN4/128, BB), 256, SM3>>>(
        s, gT, g_b, tT, MM, CIc, CIc,
        (size_t)NN4*MM, (size_t)MM*CIc, (size_t)NN4*CIc);
    // z' (c, b*n) = wz_w @ tT^T  [3x tf32]; bias along M(c)
    gemm_mma<128,1,true,false,false><<<dim3((BB*NN4)/128, CC/128, 1), 256, SM3>>>(
        wz_w, tT, wz_b, zP, CIc, CIc, BB*NN4, 0, 0, 0);

    stats_kernel<<<CC, 256>>>(zP, stats);
    finalize_kernel<<<(BB*CC*NN4/4)/256, 256>>>(x, zP, stats, gamma, beta, out);
}

// round 7
// speedup vs baseline: 1.2648x; 1.2648x over previous
#include <cuda_runtime.h>
#include <math.h>

#define BB 8
#define CC 256
#define CIc 128
#define HH 64
#define WW 64
#define NN4 4096
#define MM 1024
#define EPSF 1e-5f
#define SCALE 0.08838834764831845f  // 1/sqrt(128)

// -------- scratch (static device globals; no allocation) --------
__device__ float d_xp[BB*CC*MM];
__device__ float d_theta[BB*CIc*NN4];
__device__ float d_phi[BB*CIc*MM];
__device__ float d_g[BB*CIc*MM];
__device__ float d_s[(size_t)BB*NN4*MM];   // scores / probs (134MB)
__device__ float d_t[BB*CIc*NN4];
__device__ float d_z[BB*CC*NN4];
__device__ float d_stats[2*CC];

// -------- helpers --------
__device__ __forceinline__ unsigned f2tf(float f){
    unsigned r; asm("cvt.rna.tf32.f32 %0, %1;" : "=r"(r) : "f"(f)); return r;
}
__device__ __forceinline__ void tfsplit(float v, unsigned &hi, unsigned &lo){
    hi = f2tf(v);
    lo = f2tf(v - __uint_as_float(hi));
}
__device__ __forceinline__ void mma_tf32(float c[4], unsigned a0, unsigned a1,
                                         unsigned a2, unsigned a3,
                                         unsigned b0, unsigned b1){
    asm("mma.sync.aligned.m16n8k8.row.col.f32.tf32.tf32.f32 "
        "{%0,%1,%2,%3},{%4,%5,%6,%7},{%8,%9},{%0,%1,%2,%3};"
        : "+f"(c[0]), "+f"(c[1]), "+f"(c[2]), "+f"(c[3])
        : "r"(a0), "r"(a1), "r"(a2), "r"(a3), "r"(b0), "r"(b1));
}
__device__ __forceinline__ void mma3(float c[4],
        const unsigned ah[4], const unsigned al[4],
        unsigned bh0, unsigned bh1, unsigned bl0, unsigned bl1){
    mma_tf32(c, ah[0],ah[1],ah[2],ah[3], bh0,bh1);
    mma_tf32(c, ah[0],ah[1],ah[2],ah[3], bl0,bl1);
    mma_tf32(c, al[0],al[1],al[2],al[3], bh0,bh1);
}

// -------- 2x2 maxpool stride 2 --------
__global__ void pool_kernel(const float* __restrict__ x, float* __restrict__ xp){
    int e = blockIdx.x*256 + threadIdx.x;
    int p = e & 1023; int bc = e >> 10;
    int i = p >> 5, j = p & 31;
    const float* base = x + ((bc*HH + 2*i)*WW + 2*j);
    xp[e] = fmaxf(fmaxf(base[0], base[1]), fmaxf(base[WW], base[WW+1]));
}

// -------- 1x1 conv, tf32 (1x or 3x), split-at-store --------
// block 64(M) x 128(N), 8 warps 2x4, warp 32x32. smem hi(/lo) planes.
#define CWP 72
#define CXP 136
#define CONV_U32_3X (32*CWP*2 + 32*CXP*2)
#define CONV_U32_1X (32*CWP + 32*CXP)
template<int CO, int CIN, int NPIX, bool S3>
__global__ __launch_bounds__(256) void conv_mma(
        const float* __restrict__ X, const float* __restrict__ Wt,
        const float* __restrict__ bias, float* __restrict__ Y){
    extern __shared__ unsigned dy[];
    unsigned (*Wh)[CWP] = (unsigned(*)[CWP])dy;
    unsigned (*Wl)[CWP] = (unsigned(*)[CWP])(dy + 32*CWP);            // S3 only
    unsigned (*Xh)[CXP] = (unsigned(*)[CXP])(dy + (S3 ? 64*CWP : 32*CWP));
    unsigned (*Xl)[CXP] = (unsigned(*)[CXP])(dy + 64*CWP + 32*CXP);   // S3 only
    int b = blockIdx.z;
    const float* Xb = X + (size_t)b*CIN*NPIX;
    float* Yb = Y + (size_t)b*CO*NPIX;
    int m0b = blockIdx.y*64, n0b = blockIdx.x*128;
    int tid = threadIdx.x;
    int w = tid >> 5, lane = tid & 31;
    int gg = lane >> 2, t4 = lane & 3;
    int m_base = (w >> 2)*32, n_base = (w & 3)*32;
    float acc[2][4][4] = {};
    int wm = tid & 63, wkg = (tid >> 6)*8;
    int xr = tid >> 3, xc0 = (tid & 7)*4;
    for (int k0 = 0; k0 < CIN; k0 += 32){
        __syncthreads();
        {
            const float* wp = &Wt[(m0b+wm)*CIN + k0 + wkg];
            float4 v0 = *(const float4*)wp;
            float4 v1 = *(const float4*)(wp+4);
            float vv[8] = {v0.x,v0.y,v0.z,v0.w,v1.x,v1.y,v1.z,v1.w};
            #pragma unroll
            for (int q = 0; q < 8; q++){
                if (S3){
                    unsigned h,l; tfsplit(vv[q],h,l);
                    Wh[wkg+q][wm]=h; Wl[wkg+q][wm]=l;
                } else {
                    Wh[wkg+q][wm]=f2tf(vv[q]);
                }
            }
        }
        #pragma unroll
        for (int j = 0; j < 4; j++){
            float4 v = *(const float4*)&Xb[(size_t)(k0+xr)*NPIX + n0b + xc0 + 32*j];
            if (S3){
                uint4 h, l;
                tfsplit(v.x, h.x, l.x); tfsplit(v.y, h.y, l.y);
                tfsplit(v.z, h.z, l.z); tfsplit(v.w, h.w, l.w);
                *(uint4*)&Xh[xr][xc0+32*j] = h;
                *(uint4*)&Xl[xr][xc0+32*j] = l;
            } else {
                uint4 h = make_uint4(f2tf(v.x), f2tf(v.y), f2tf(v.z), f2tf(v.w));
                *(uint4*)&Xh[xr][xc0+32*j] = h;
            }
        }
        __syncthreads();
        #pragma unroll
        for (int kc = 0; kc < 4; kc++){
            int k8 = kc*8;
            unsigned ah[2][4], al[2][4];
            #pragma unroll
            for (int mt = 0; mt < 2; mt++){
                int m = m_base + mt*16 + gg;
                ah[mt][0]=Wh[k8+t4  ][m];   ah[mt][1]=Wh[k8+t4  ][m+8];
                ah[mt][2]=Wh[k8+t4+4][m];   ah[mt][3]=Wh[k8+t4+4][m+8];
                if (S3){
                    al[mt][0]=Wl[k8+t4  ][m];   al[mt][1]=Wl[k8+t4  ][m+8];
                    al[mt][2]=Wl[k8+t4+4][m];   al[mt][3]=Wl[k8+t4+4][m+8];
                }
            }
            #pragma unroll
            for (int nt = 0; nt < 4; nt++){
                int n = n_base + nt*8 + gg;
                unsigned bh0=Xh[k8+t4][n], bh1=Xh[k8+t4+4][n];
                if (S3){
                    unsigned bl0=Xl[k8+t4][n], bl1=Xl[k8+t4+4][n];
                    mma3(acc[0][nt], ah[0], al[0], bh0,bh1,bl0,bl1);
                    mma3(acc[1][nt], ah[1], al[1], bh0,bh1,bl0,bl1);
                } else {
                    mma_tf32(acc[0][nt], ah[0][0],ah[0][1],ah[0][2],ah[0][3], bh0,bh1);
                    mma_tf32(acc[1][nt], ah[1][0],ah[1][1],ah[1][2],ah[1][3], bh0,bh1);
                }
            }
        }
    }
    #pragma unroll
    for (int mt = 0; mt < 2; mt++){
        int mrow0 = m0b + m_base + mt*16 + gg;
        float b0v = bias[mrow0], b1v = bias[mrow0+8];
        #pragma unroll
        for (int nt = 0; nt < 4; nt++){
            int col = n0b + n_base + nt*8 + 2*t4;
            *(float2*)&Yb[(size_t)mrow0*NPIX + col] =
                make_float2(acc[mt][nt][0]+b0v, acc[mt][nt][1]+b0v);
            *(float2*)&Yb[(size_t)(mrow0+8)*NPIX + col] =
                make_float2(acc[mt][nt][2]+b1v, acc[mt][nt][3]+b1v);
        }
    }
}

// -------- scores: S[b](4096,1024) = (theta^T * SCALE) @ phi  [1x tf32] --------
// block 128x128, 8 warps 4x2, warp 32x64. K=128 (ci).
#define GP 136
#define SC_U32 (2*32*GP)
__global__ __launch_bounds__(256) void score_mma(
        const float* __restrict__ theta, const float* __restrict__ phi,
        float* __restrict__ S){
    extern __shared__ unsigned dy[];
    unsigned (*Ah)[GP] = (unsigned(*)[GP])dy;
    unsigned (*Bh)[GP] = (unsigned(*)[GP])(dy + 32*GP);
    int b = blockIdx.z;
    const float* thb = theta + (size_t)b*CIc*NN4;
    const float* phb = phi   + (size_t)b*CIc*MM;
    float* Sb = S + (size_t)b*NN4*MM;
    int m0 = blockIdx.y*128, n0 = blockIdx.x*128;
    int tid = threadIdx.x, w = tid >> 5, lane = tid & 31;
    int gg = lane >> 2, t4 = lane & 3;
    int wm = (w >> 1)*32, wn = (w & 1)*64;
    float acc[2][8][4] = {};
    int r = tid >> 3, c0 = (tid & 7)*4;
    #pragma unroll 1
    for (int k0 = 0; k0 < CIc; k0 += 32){
        __syncthreads();
        #pragma unroll
        for (int j = 0; j < 4; j++){
            float4 va = *(const float4*)&thb[(size_t)(k0+r)*NN4 + m0 + c0 + 32*j];
            *(uint4*)&Ah[r][c0+32*j] = make_uint4(
                f2tf(va.x*SCALE), f2tf(va.y*SCALE), f2tf(va.z*SCALE), f2tf(va.w*SCALE));
            float4 vb = *(const float4*)&phb[(size_t)(k0+r)*MM + n0 + c0 + 32*j];
            *(uint4*)&Bh[r][c0+32*j] = make_uint4(
                f2tf(vb.x), f2tf(vb.y), f2tf(vb.z), f2tf(vb.w));
        }
        __syncthreads();
        #pragma unroll
        for (int kc = 0; kc < 4; kc++){
            int k8 = kc*8;
            unsigned ah[2][4];
            #pragma unroll
            for (int mt = 0; mt < 2; mt++){
                int m = wm + mt*16 + gg;
                ah[mt][0]=Ah[k8+t4  ][m];   ah[mt][1]=Ah[k8+t4  ][m+8];
                ah[mt][2]=Ah[k8+t4+4][m];   ah[mt][3]=Ah[k8+t4+4][m+8];
            }
            #pragma unroll
            for (int nt = 0; nt < 8; nt++){
                int n = wn + nt*8 + gg;
                unsigned bh0=Bh[k8+t4][n], bh1=Bh[k8+t4+4][n];
                mma_tf32(acc[0][nt], ah[0][0],ah[0][1],ah[0][2],ah[0][3], bh0,bh1);
                mma_tf32(acc[1][nt], ah[1][0],ah[1][1],ah[1][2],ah[1][3], bh0,bh1);
            }
        }
    }
    #pragma unroll
    for (int mt = 0; mt < 2; mt++){
        int row0 = m0 + wm + mt*16 + gg;
        #pragma unroll
        for (int nt = 0; nt < 8; nt++){
            int col = n0 + wn + nt*8 + 2*t4;
            *(float2*)&Sb[(size_t)row0*MM + col] =
                make_float2(acc[mt][nt][0], acc[mt][nt][1]);
            *(float2*)&Sb[(size_t)(row0+8)*MM + col] =
                make_float2(acc[mt][nt][2], acc[mt][nt][3]);
        }
    }
}

// -------- softmax rows in place: 8 rows per 256-thr block --------
__global__ void softmax_kernel(float* __restrict__ S){
    int row = blockIdx.x*8 + (threadIdx.x >> 5);
    int lane = threadIdx.x & 31;
    float4* rp = (float4*)(S + (size_t)row*MM);
    float4 v[8];
    float mx = -1e30f;
    #pragma unroll
    for (int j = 0; j < 8; j++){
        v[j] = rp[lane + 32*j];
        mx = fmaxf(mx, fmaxf(fmaxf(v[j].x, v[j].y), fmaxf(v[j].z, v[j].w)));
    }
    #pragma unroll
    for (int o = 16; o; o >>= 1) mx = fmaxf(mx, __shfl_xor_sync(0xffffffffu, mx, o));
    float sum = 0.f;
    #pragma unroll
    for (int j = 0; j < 8; j++){
        v[j].x = __expf(v[j].x - mx); v[j].y = __expf(v[j].y - mx);
        v[j].z = __expf(v[j].z - mx); v[j].w = __expf(v[j].w - mx);
        sum += v[j].x + v[j].y + v[j].z + v[j].w;
    }
    #pragma unroll
    for (int o = 16; o; o >>= 1) sum += __shfl_xor_sync(0xffffffffu, sum, o);
    float inv = 1.f/sum;
    #pragma unroll
    for (int j = 0; j < 8; j++){
        v[j].x *= inv; v[j].y *= inv; v[j].z *= inv; v[j].w *= inv;
        rp[lane + 32*j] = v[j];
    }
}

// -------- t[b](128,4096) = g(128,1024) @ P^T(1024,4096)  [3x tf32] --------
// block 128(M=ci) x 128(N=q), 8 warps 4x2, warp 32x64. K=1024 chunks of 32.
#define PBP 36
#define PV_U32 (2*32*GP + 2*128*PBP)
__global__ __launch_bounds__(256) void pv_mma(
        const float* __restrict__ g, const float* __restrict__ P,
        float* __restrict__ T){
    extern __shared__ unsigned dy[];
    unsigned (*Ah)[GP]  = (unsigned(*)[GP])dy;
    unsigned (*Al)[GP]  = (unsigned(*)[GP])(dy + 32*GP);
    unsigned (*Bh)[PBP] = (unsigned(*)[PBP])(dy + 64*GP);
    unsigned (*Bl)[PBP] = (unsigned(*)[PBP])(dy + 64*GP + 128*PBP);
    int b = blockIdx.z;
    const float* gb = g + (size_t)b*CIc*MM;
    const float* Pb = P + (size_t)b*NN4*MM;
    float* Tb = T + (size_t)b*CIc*NN4;
    int n0 = blockIdx.x*128;
    int tid = threadIdx.x, w = tid >> 5, lane = tid & 31;
    int gg = lane >> 2, t4 = lane & 3;
    int wm = (w >> 1)*32, wn = (w & 1)*64;
    float acc[2][8][4] = {};
    int aci = tid >> 1, ak0 = (tid & 1)*16;
    int bn = tid >> 3, bk0 = (tid & 7)*4;
    #pragma unroll 1
    for (int k0 = 0; k0 < MM; k0 += 32){
        __syncthreads();
        #pragma unroll
        for (int j = 0; j < 4; j++){
            float4 v = *(const float4*)&gb[(size_t)aci*MM + k0 + ak0 + 4*j];
            unsigned h,l; int kk = ak0 + 4*j;
            tfsplit(v.x,h,l); Ah[kk+0][aci]=h; Al[kk+0][aci]=l;
            tfsplit(v.y,h,l); Ah[kk+1][aci]=h; Al[kk+1][aci]=l;
            tfsplit(v.z,h,l); Ah[kk+2][aci]=h; Al[kk+2][aci]=l;
            tfsplit(v.w,h,l); Ah[kk+3][aci]=h; Al[kk+3][aci]=l;
        }
        #pragma unroll
        for (int p = 0; p < 4; p++){
            int n = bn + 32*p;
            float4 v = *(const float4*)&Pb[(size_t)(n0+n)*MM + k0 + bk0];
            uint4 h, l;
            tfsplit(v.x, h.x, l.x); tfsplit(v.y, h.y, l.y);
            tfsplit(v.z, h.z, l.z); tfsplit(v.w, h.w, l.w);
            *(uint4*)&Bh[n][bk0] = h;
            *(uint4*)&Bl[n][bk0] = l;
        }
        __syncthreads();
        #pragma unroll
        for (int kc = 0; kc < 4; kc++){
            int k8 = kc*8;
            unsigned ah[2][4], al[2][4];
            #pragma unroll
            for (int mt = 0; mt < 2; mt++){
                int m = wm + mt*16 + gg;
                ah[mt][0]=Ah[k8+t4  ][m];   al[mt][0]=Al[k8+t4  ][m];
                ah[mt][1]=Ah[k8+t4  ][m+8]; al[mt][1]=Al[k8+t4  ][m+8];
                ah[mt][2]=Ah[k8+t4+4][m];   al[mt][2]=Al[k8+t4+4][m];
                ah[mt][3]=Ah[k8+t4+4][m+8]; al[mt][3]=Al[k8+t4+4][m+8];
            }
            #pragma unroll
            for (int nt = 0; nt < 8; nt++){
                int n = wn + nt*8 + gg;
                unsigned bh0=Bh[n][k8+t4], bh1=Bh[n][k8+t4+4];
                unsigned bl0=Bl[n][k8+t4], bl1=Bl[n][k8+t4+4];
                mma3(acc[0][nt], ah[0], al[0], bh0,bh1,bl0,bl1);
                mma3(acc[1][nt], ah[1], al[1], bh0,bh1,bl0,bl1);
            }
        }
    }
    #pragma unroll
    for (int mt = 0; mt < 2; mt++){
        int row0 = wm + mt*16 + gg;
        #pragma unroll
        for (int nt = 0; nt < 8; nt++){
            int col = n0 + wn + nt*8 + 2*t4;
            *(float2*)&Tb[(size_t)row0*NN4 + col] =
                make_float2(acc[mt][nt][0], acc[mt][nt][1]);
            *(float2*)&Tb[(size_t)(row0+8)*NN4 + col] =
                make_float2(acc[mt][nt][2], acc[mt][nt][3]);
        }
    }
}

// -------- per-channel batch statistics (fp64 accumulate, deterministic) --------
__global__ void stats_kernel(const float* __restrict__ z, float* __restrict__ stats){
    __shared__ double sd[256], sd2[256];
    int c = blockIdx.x, tid = threadIdx.x;
    double s = 0.0, s2 = 0.0;
    for (int i = tid; i < BB*NN4; i += 256){
        int b = i >> 12, n = i & 4095;
        float v = z[((size_t)b*CC + c)*NN4 + n];
        s += v; s2 += (double)v*v;
    }
    sd[tid] = s; sd2[tid] = s2;
    __syncthreads();
    for (int o = 128; o; o >>= 1){
        if (tid < o){ sd[tid] += sd[tid+o]; sd2[tid] += sd2[tid+o]; }
        __syncthreads();
    }
    if (tid == 0){
        double cnt = (double)(BB*NN4);
        double mean = sd[0]/cnt;
        double var  = sd2[0]/cnt - mean*mean;
        stats[c]      = (float)mean;
        stats[CC + c] = rsqrtf((float)var + EPSF);
    }
}

// -------- normalize + affine + residual --------
__global__ void finalize_kernel(const float* __restrict__ x, const float* __restrict__ z,
                                const float* __restrict__ stats,
                                const float* __restrict__ gamma, const float* __restrict__ beta,
                                float* __restrict__ out){
    int i4 = blockIdx.x*256 + threadIdx.x;
    int c = (i4 >> 10) & 255;
    float a  = stats[CC + c] * gamma[c];
    float bc = beta[c] - stats[c]*a;
    float4 xv = ((const float4*)x)[i4];
    float4 zv = ((const float4*)z)[i4];
    float4 o;
    o.x = xv.x + zv.x*a + bc;
    o.y = xv.y + zv.y*a + bc;
    o.z = xv.z + zv.z*a + bc;
    o.w = xv.w + zv.w*a + bc;
    ((float4*)out)[i4] = o;
}

extern "C" void kernel_launch(void* const* d_in, const int* in_sizes, int n_in,
                              void* d_out, int out_size){
    const float* x       = (const float*)d_in[0];
    const float* theta_w = (const float*)d_in[1];
    const float* theta_b = (const float*)d_in[2];
    const float* phi_w   = (const float*)d_in[3];
    const float* phi_b   = (const float*)d_in[4];
    const float* g_w     = (const float*)d_in[5];
    const float* g_b     = (const float*)d_in[6];
    const float* wz_w    = (const float*)d_in[7];
    const float* wz_b    = (const float*)d_in[8];
    const float* gamma   = (const float*)d_in[9];
    const float* beta    = (const float*)d_in[10];
    float* out = (float*)d_out;

    float *xp, *theta, *phi, *g, *s, *t, *z, *stats;
    cudaGetSymbolAddress((void**)&xp,    d_xp);
    cudaGetSymbolAddress((void**)&theta, d_theta);
    cudaGetSymbolAddress((void**)&phi,   d_phi);
    cudaGetSymbolAddress((void**)&g,     d_g);
    cudaGetSymbolAddress((void**)&s,     d_s);
    cudaGetSymbolAddress((void**)&t,     d_t);
    cudaGetSymbolAddress((void**)&z,     d_z);
    cudaGetSymbolAddress((void**)&stats, d_stats);

    cudaFuncSetAttribute(conv_mma<CIc, CC, NN4, false>,
        cudaFuncAttributeMaxDynamicSharedMemorySize, CONV_U32_1X*4);
    cudaFuncSetAttribute(conv_mma<CIc, CC, MM, false>,
        cudaFuncAttributeMaxDynamicSharedMemorySize, CONV_U32_1X*4);
    cudaFuncSetAttribute(conv_mma<CIc, CC, MM, true>,
        cudaFuncAttributeMaxDynamicSharedMemorySize, CONV_U32_3X*4);
    cudaFuncSetAttribute(conv_mma<CC, CIc, NN4, true>,
        cudaFuncAttributeMaxDynamicSharedMemorySize, CONV_U32_3X*4);
    cudaFuncSetAttribute(score_mma,
        cudaFuncAttributeMaxDynamicSharedMemorySize, SC_U32*4);
    cudaFuncSetAttribute(pv_mma,
        cudaFuncAttributeMaxDynamicSharedMemorySize, PV_U32*4);

    pool_kernel<<<(BB*CC*MM)/256, 256>>>(x, xp);
    conv_mma<CIc, CC, NN4, false><<<dim3(NN4/128, CIc/64, BB), 256, CONV_U32_1X*4>>>(
        x,  theta_w, theta_b, theta);
    conv_mma<CIc, CC, MM, false><<<dim3(MM/128,  CIc/64, BB), 256, CONV_U32_1X*4>>>(
        xp, phi_w,   phi_b,   phi);
    conv_mma<CIc, CC, MM, true><<<dim3(MM/128,  CIc/64, BB), 256, CONV_U32_3X*4>>>(
        xp, g_w,     g_b,     g);
    score_mma<<<dim3(MM/128, NN4/128, BB), 256, SC_U32*4>>>(theta, phi, s);
    softmax_kernel<<<(BB*NN4)/8, 256>>>(s);
    pv_mma<<<dim3(NN4/128, 1, BB), 256, PV_U32*4>>>(g, s, t);
    conv_mma<CC, CIc, NN4, true><<<dim3(NN4/128, CC/64, BB), 256, CONV_U32_3X*4>>>(
        t, wz_w, wz_b, z);
    stats_kernel<<<CC, 256>>>(z, stats);
    finalize_kernel<<<(BB*CC*NN4/4)/256, 256>>>(x, z, stats, gamma, beta, out);
}